// round 5
// baseline (speedup 1.0000x reference)
#include <cuda_runtime.h>
#include <math.h>

#define B_ 8
#define N_ 2048
#define F_ 256
#define K_ 205
#define ACAP 256
#define CSRCAP 128
#define SROWCAP 130
#define ROWS_ (B_*N_)

// output layout (floats): [xc | coarse | S | topi]
#define XC_OFF 0
#define CO_OFF ((size_t)B_*N_*F_)
#define SO_OFF (CO_OFF + (size_t)B_*N_*N_)
#define TI_OFF (SO_OFF + (size_t)B_*N_*N_)
#define FRONT4 (SO_OFF/4)              // float4 count of [xc+coarse)
#define SREG4  (((size_t)B_*N_*N_)/4)  // float4 count of S region

#define AZB 8192   // zero blocks appended to k_alpha (256 thr)
#define TZB 2048   // zero blocks appended to k_topk  (1024 thr)

// ---- static scratch ----
__device__ float g_t[ROWS_];
__device__ float g_radj[ROWS_];
__device__ float g_adiag[ROWS_];
__device__ float g_dg[ROWS_];
__device__ float g_alpha[ROWS_];
__device__ int   g_ccol[ROWS_*CSRCAP];
__device__ float g_cval[ROWS_*CSRCAP];
__device__ int   g_ccnt[ROWS_];
__device__ int   g_sj[ROWS_*SROWCAP];
__device__ float g_sv[ROWS_*SROWCAP];
__device__ int   g_scnt[ROWS_];
__device__ int   g_colid[B_*ACAP];
__device__ float g_w[B_*ACAP];
__device__ int   g_acnt[B_];
__device__ int   g_rank[ROWS_];
__device__ float g_T[(size_t)ROWS_*ACAP];

// ---- KA: {CSR+rowsum+diag+dg} | {t = x@W}  (float4 loads, warp-scan compaction) ----
__global__ void kA(const float* __restrict__ adj, const float* __restrict__ x,
                   const float* __restrict__ W){
    int blk = blockIdx.x;
    int lane = threadIdx.x & 31;
    if (blk < 2048) {
        int row = blk * 8 + (threadIdx.x >> 5);
        int n = row % N_;
        const float4* ar4 = (const float4*)(adj + (size_t)row * N_);
        float sum = 0.f, diag = 0.f;
        int cnt = 0, base = row * CSRCAP;
        #pragma unroll 4
        for (int c4 = lane; c4 < N_/4; c4 += 32) {
            float4 a = ar4[c4];
            float va[4] = {a.x, a.y, a.z, a.w};
            int col0 = c4 * 4;
            sum += va[0] + va[1] + va[2] + va[3];
            if (n >= col0 && n < col0 + 4) diag = va[n - col0];
            int k = (va[0]!=0.f) + (va[1]!=0.f) + (va[2]!=0.f) + (va[3]!=0.f);
            // warp inclusive scan of k
            int inc = k;
            #pragma unroll
            for (int d = 1; d < 32; d <<= 1) {
                int v = __shfl_up_sync(0xffffffffu, inc, d);
                if (lane >= d) inc += v;
            }
            int tot = __shfl_sync(0xffffffffu, inc, 31);
            int pos = cnt + inc - k;
            #pragma unroll
            for (int q = 0; q < 4; q++) {
                if (va[q] != 0.f) {
                    if (pos < CSRCAP) { g_ccol[base+pos] = col0+q; g_cval[base+pos] = va[q]; }
                    pos++;
                }
            }
            cnt += tot;
        }
        #pragma unroll
        for (int o = 16; o; o >>= 1) {
            sum  += __shfl_xor_sync(0xffffffffu, sum,  o);
            diag += __shfl_xor_sync(0xffffffffu, diag, o);
        }
        if (lane == 0) {
            g_radj[row] = sum;
            g_adiag[row] = diag;
            g_ccnt[row] = cnt < CSRCAP ? cnt : CSRCAP;
            g_dg[row] = rsqrtf(sum + 1.f);
        }
    } else {
        // t = x @ W, one warp per row (float4)
        int row = (blk - 2048) * 8 + (threadIdx.x >> 5);
        const float4* xr4 = (const float4*)(x + (size_t)row * F_);
        const float4* W4 = (const float4*)W;
        float s = 0.f;
        #pragma unroll
        for (int f = lane; f < F_/4; f += 32) {
            float4 xv = xr4[f]; float4 wv = W4[f];
            s += xv.x*wv.x + xv.y*wv.y + xv.z*wv.z + xv.w*wv.w;
        }
        #pragma unroll
        for (int o = 16; o; o >>= 1) s += __shfl_xor_sync(0xffffffffu, s, o);
        if (lane == 0) g_t[row] = s;
    }
}

// ---- KB: alpha | zero S region ----
__global__ void k_alpha(const float* __restrict__ bptr, float* __restrict__ S_out){
    int blk = blockIdx.x;
    if (blk >= 2048) {
        size_t i = (size_t)(blk - 2048) * 256 + threadIdx.x;
        float4 z = make_float4(0.f,0.f,0.f,0.f);
        float4* o4 = (float4*)S_out;
        size_t stride = (size_t)AZB * 256;
        for (; i < SREG4; i += stride) o4[i] = z;
        return;
    }
    int row = blk * 8 + (threadIdx.x >> 5);
    int lane = threadIdx.x & 31;
    int bN = (row / N_) * N_;
    int base = row * CSRCAP;
    int cnt = g_ccnt[row];
    float s = 0.f;
    for (int e = lane; e < cnt; e += 32) {
        int m = g_ccol[base + e];
        s += g_cval[base + e] * __ldg(&g_dg[bN + m]) * __ldg(&g_t[bN + m]);
    }
    #pragma unroll
    for (int o = 16; o; o >>= 1) s += __shfl_xor_sync(0xffffffffu, s, o);
    if (lane == 0) {
        s += g_dg[row] * g_t[row];            // identity part of A_hat
        float pre = g_dg[row] * s + bptr[0];
        float z = pre * pre;
        g_alpha[row] = 1.f / (1.f + expf(-z));
    }
}

// ---- KC: per-batch top-K (bitonic, value desc / index asc) | zero xc+coarse ----
__global__ void k_topk(float* __restrict__ out_all){
    int blk = blockIdx.x;
    int tid = threadIdx.x;
    if (blk >= B_) {
        size_t i = (size_t)(blk - B_) * 1024 + tid;
        float4 z = make_float4(0.f,0.f,0.f,0.f);
        float4* o4 = (float4*)out_all;
        size_t stride = (size_t)TZB * 1024;
        for (; i < FRONT4; i += stride) o4[i] = z;
        return;
    }
    int b = blk;
    float* out_ti = out_all + TI_OFF;
    __shared__ unsigned long long sk[N_];
    __shared__ float cutv;
    __shared__ int acnt;
    for (int i = tid; i < N_; i += 1024) {
        g_rank[b * N_ + i] = -1;
        float v = g_alpha[b * N_ + i];
        unsigned u = __float_as_uint(v);
        u = (u & 0x80000000u) ? ~u : (u | 0x80000000u);
        sk[i] = ((unsigned long long)(~u) << 32) | (unsigned)i;
    }
    __syncthreads();
    for (int k = 2; k <= N_; k <<= 1) {
        for (int j = k >> 1; j > 0; j >>= 1) {
            for (int t = tid; t < N_; t += 1024) {
                int ixj = t ^ j;
                if (ixj > t) {
                    bool up = ((t & k) == 0);
                    unsigned long long a = sk[t], c = sk[ixj];
                    if ((a > c) == up) { sk[t] = c; sk[ixj] = a; }
                }
            }
            __syncthreads();
        }
    }
    if (tid == 0) {
        int idxK = (int)(sk[K_ - 1] & 0xffffffffu);
        cutv = g_alpha[b * N_ + idxK];
        int A = K_;
        while (A < ACAP) {
            int id = (int)(sk[A] & 0xffffffffu);
            float v = g_alpha[b * N_ + id];
            if (v + 1e-7f - cutv > 0.f) A++; else break;
        }
        acnt = A;
        g_acnt[b] = A;
    }
    __syncthreads();
    for (int j = tid; j < acnt; j += 1024) {
        int id = (int)(sk[j] & 0xffffffffu);
        g_colid[b * ACAP + j] = id;
        g_w[b * ACAP + j] = g_alpha[b * N_ + id] + 1e-7f - cutv;
        g_rank[b * N_ + id] = j;
    }
    for (int j = tid; j < K_; j += 1024) {
        int id = (int)(sk[j] & 0xffffffffu);
        out_ti[b * K_ + j] = (float)id;
    }
}

// ---- KD: build normalized S rows (sparse list + dense scatter into zeroed S) ----
__global__ void k_sbuild(float* __restrict__ S_out){
    int row = blockIdx.x * 8 + (threadIdx.x >> 5);
    if (row >= ROWS_) return;
    int lane = threadIdx.x & 31;
    int b = row / N_, n = row % N_;
    if (g_radj[row] <= 0.f) {
        if (lane == 0) g_scnt[row] = 0;
        return;
    }
    float dgn = g_dg[row];
    int cnt = g_ccnt[row], base = row * CSRCAP;
    bool hasdiag = (g_adiag[row] != 0.f);
    float rs = 0.f;
    for (int e = lane; e < cnt; e += 32) {
        int m = g_ccol[base + e];
        int j = g_rank[b * N_ + m];
        if (j >= 0) {
            float ahat = g_cval[base + e] + (m == n ? 1.f : 0.f);
            rs += dgn * ahat * g_dg[b * N_ + m] * g_w[b * ACAP + j];
        }
    }
    if (!hasdiag && lane == 0) {
        int j = g_rank[row];
        if (j >= 0) rs += dgn * dgn * g_w[b * ACAP + j];
    }
    #pragma unroll
    for (int o = 16; o; o >>= 1) rs += __shfl_xor_sync(0xffffffffu, rs, o);
    float inv = 1.f / fmaxf(rs, 1e-12f);
    int sc = 0, sbase = row * SROWCAP;
    for (int c = 0; c < cnt; c += 32) {
        int e = c + lane;
        bool act = false; int j = -1, m = -1; float v = 0.f;
        if (e < cnt) {
            m = g_ccol[base + e];
            j = g_rank[b * N_ + m];
            if (j >= 0) {
                act = true;
                float ahat = g_cval[base + e] + (m == n ? 1.f : 0.f);
                v = dgn * ahat * g_dg[b * N_ + m] * g_w[b * ACAP + j] * inv;
            }
        }
        unsigned msk = __ballot_sync(0xffffffffu, act);
        if (act) {
            int pos = sc + __popc(msk & ((1u << lane) - 1u));
            if (pos < SROWCAP) { g_sj[sbase + pos] = j; g_sv[sbase + pos] = v; }
            S_out[(size_t)row * N_ + m] = v;
        }
        sc += __popc(msk);
    }
    if (!hasdiag) {
        int add = 0;
        if (lane == 0) {
            int j = g_rank[row];
            if (j >= 0) {
                float v = dgn * dgn * g_w[b * ACAP + j] * inv;
                if (sc < SROWCAP) { g_sj[sbase + sc] = j; g_sv[sbase + sc] = v; }
                S_out[(size_t)row * N_ + n] = v;
                add = 1;
            }
        }
        sc += __shfl_sync(0xffffffffu, add, 0);
    }
    if (lane == 0) g_scnt[row] = sc < SROWCAP ? sc : SROWCAP;
}

// ---- KE: T[n,:] = sum_k adj[n,k] * Srow[k]  (warp per row, smem accumulators) ----
__global__ void k_T(){
    int w = threadIdx.x >> 5;
    int row = blockIdx.x * 8 + w;
    int lane = threadIdx.x & 31;
    __shared__ float acc[8][ACAP];
    float* a = acc[w];
    for (int i = lane; i < ACAP; i += 32) a[i] = 0.f;
    __syncwarp();
    int b = row / N_;
    int cnt = g_ccnt[row], base = row * CSRCAP;
    for (int e = lane; e < cnt; e += 32) {
        int k = g_ccol[base + e];
        float av = g_cval[base + e];
        size_t krow = (size_t)b * N_ + k;
        int sb = (int)krow * SROWCAP;
        int sc = g_scnt[krow];
        for (int q = 0; q < sc; q++)
            atomicAdd(&a[g_sj[sb + q]], av * g_sv[sb + q]);
    }
    __syncwarp();
    int A = g_acnt[b];
    float* Trow = g_T + (size_t)row * ACAP;
    for (int j = lane; j < A; j += 32) Trow[j] = a[j];
}

// ---- KF: fused coarse + x_c, chunked smem staging of T/x rows ----
#define CH 32
__global__ void __launch_bounds__(256) k_cx(
        const float* __restrict__ x, const float* __restrict__ S_out,
        float* __restrict__ out_co, float* __restrict__ out_xc){
    int b = blockIdx.y;
    int jm = blockIdx.x;
    int A = g_acnt[b];
    if (jm >= A) return;
    int tid = threadIdx.x;
    int m = g_colid[b * ACAP + jm];
    size_t bN = (size_t)b * N_;
    size_t mrow = bN + m;
    __shared__ int   sn[CSRCAP + 1];
    __shared__ float sv[CSRCAP + 1];
    __shared__ float sT[CH * ACAP];
    __shared__ float sX[CH * F_];
    int cnt = g_ccnt[mrow], base = (int)mrow * CSRCAP;
    if (tid < cnt) {
        int n2 = g_ccol[base + tid];
        sn[tid] = n2;
        sv[tid] = S_out[(bN + n2) * N_ + m];   // symmetry: col m pattern = row m
    }
    int tot = cnt;
    if (g_adiag[mrow] == 0.f) {
        if (tid == 0) { sn[cnt] = m; sv[cnt] = S_out[mrow * N_ + m]; }
        tot = cnt + 1;
    }
    __syncthreads();
    float accC = 0.f, accX = 0.f;
    for (int e0 = 0; e0 < tot; e0 += CH) {
        int ce = tot - e0; if (ce > CH) ce = CH;
        for (int r = 0; r < ce; r++) {
            size_t nr = bN + sn[e0 + r];
            sT[r * ACAP + tid] = g_T[nr * ACAP + tid];
            sX[r * F_   + tid] = x[nr * F_ + tid];
        }
        __syncthreads();
        for (int r = 0; r < ce; r++) {
            float w = sv[e0 + r];
            accC += w * sT[r * ACAP + tid];
            accX += w * sX[r * F_   + tid];
        }
        __syncthreads();
    }
    out_xc[mrow * F_ + tid] = accX;
    if (tid < A) {
        float c = floorf(accC * 10000.0f) / 10000.0f;
        int l = g_colid[b * ACAP + tid];
        out_co[mrow * N_ + l] = c;
    }
}

extern "C" void kernel_launch(void* const* d_in, const int* in_sizes, int n_in,
                              void* d_out, int out_size) {
    const float* x   = (const float*)d_in[0];
    const float* adj = (const float*)d_in[1];
    const float* W   = (const float*)d_in[2];
    const float* bb  = (const float*)d_in[3];
    float* out = (float*)d_out;

    kA      <<<4096, 256>>>(adj, x, W);
    k_alpha <<<2048 + AZB, 256>>>(bb, out + SO_OFF);
    k_topk  <<<B_ + TZB, 1024>>>(out);
    k_sbuild<<<ROWS_ / 8, 256>>>(out + SO_OFF);
    k_T     <<<ROWS_ / 8, 256>>>();
    dim3 gblk(ACAP, B_);
    k_cx    <<<gblk, 256>>>(x, out + SO_OFF, out + CO_OFF, out + XC_OFF);
}

// round 6
// speedup vs baseline: 1.3036x; 1.3036x over previous
#include <cuda_runtime.h>
#include <math.h>

#define B_ 8
#define N_ 2048
#define F_ 256
#define K_ 205
#define ACAP 256
#define CSRCAP 128
#define SROWCAP 130
#define ROWS_ (B_*N_)

// output layout (floats): [xc | coarse | S | topi]
#define XC_OFF 0
#define CO_OFF ((size_t)B_*N_*F_)
#define SO_OFF (CO_OFF + (size_t)B_*N_*N_)
#define TI_OFF (SO_OFF + (size_t)B_*N_*N_)
#define FRONT4 (SO_OFF/4)              // float4 count of [xc+coarse)
#define SREG4  (((size_t)B_*N_*N_)/4)  // float4 count of S region

#define AZB 8192   // zero blocks appended to k_alpha (256 thr)
#define TZB 2048   // zero blocks appended to k_topk  (1024 thr)

// ---- static scratch ----
__device__ float g_t[ROWS_];
__device__ float g_radj[ROWS_];
__device__ float g_adiag[ROWS_];
__device__ float g_dg[ROWS_];
__device__ float g_alpha[ROWS_];
__device__ int   g_ccol[ROWS_*CSRCAP];
__device__ float g_cval[ROWS_*CSRCAP];
__device__ int   g_ccnt[ROWS_];
__device__ int   g_sj[ROWS_*SROWCAP];
__device__ float g_sv[ROWS_*SROWCAP];
__device__ int   g_scnt[ROWS_];
__device__ int   g_colid[B_*ACAP];
__device__ float g_w[B_*ACAP];
__device__ int   g_acnt[B_];
__device__ int   g_rank[ROWS_];
__device__ float g_T[(size_t)ROWS_*ACAP];

// ---- KA: {CSR+rowsum+diag+dg} | {t = x@W}  (float4 loads, ballot compaction) ----
__global__ void kA(const float* __restrict__ adj, const float* __restrict__ x,
                   const float* __restrict__ W){
    int blk = blockIdx.x;
    int lane = threadIdx.x & 31;
    if (blk < 2048) {
        int row = blk * 8 + (threadIdx.x >> 5);
        int n = row % N_;
        const float4* ar4 = (const float4*)(adj + (size_t)row * N_);
        float sum = 0.f, diag = 0.f;
        int cnt = 0, base = row * CSRCAP;
        #pragma unroll 4
        for (int c4 = lane; c4 < N_/4; c4 += 32) {
            float4 a = ar4[c4];
            float va[4] = {a.x, a.y, a.z, a.w};
            int col0 = c4 * 4;
            sum += va[0] + va[1] + va[2] + va[3];
            if ((n >> 2) == c4) diag = va[n & 3];
            #pragma unroll
            for (int q = 0; q < 4; q++) {
                float v = va[q];
                unsigned msk = __ballot_sync(0xffffffffu, v != 0.f);
                if (v != 0.f) {
                    int pos = cnt + __popc(msk & ((1u << lane) - 1u));
                    if (pos < CSRCAP) { g_ccol[base + pos] = col0 + q; g_cval[base + pos] = v; }
                }
                cnt += __popc(msk);
            }
        }
        #pragma unroll
        for (int o = 16; o; o >>= 1) {
            sum  += __shfl_xor_sync(0xffffffffu, sum,  o);
            diag += __shfl_xor_sync(0xffffffffu, diag, o);
        }
        if (lane == 0) {
            g_radj[row] = sum;
            g_adiag[row] = diag;
            g_ccnt[row] = cnt < CSRCAP ? cnt : CSRCAP;
            g_dg[row] = rsqrtf(sum + 1.f);
        }
    } else {
        // t = x @ W, one warp per row (float4)
        int row = (blk - 2048) * 8 + (threadIdx.x >> 5);
        const float4* xr4 = (const float4*)(x + (size_t)row * F_);
        const float4* W4 = (const float4*)W;
        float s = 0.f;
        #pragma unroll
        for (int f = lane; f < F_/4; f += 32) {
            float4 xv = xr4[f]; float4 wv = W4[f];
            s += xv.x*wv.x + xv.y*wv.y + xv.z*wv.z + xv.w*wv.w;
        }
        #pragma unroll
        for (int o = 16; o; o >>= 1) s += __shfl_xor_sync(0xffffffffu, s, o);
        if (lane == 0) g_t[row] = s;
    }
}

// ---- KB: alpha | zero S region ----
__global__ void k_alpha(const float* __restrict__ bptr, float* __restrict__ S_out){
    int blk = blockIdx.x;
    if (blk >= 2048) {
        size_t i = (size_t)(blk - 2048) * 256 + threadIdx.x;
        float4 z = make_float4(0.f,0.f,0.f,0.f);
        float4* o4 = (float4*)S_out;
        size_t stride = (size_t)AZB * 256;
        for (; i < SREG4; i += stride) o4[i] = z;
        return;
    }
    int row = blk * 8 + (threadIdx.x >> 5);
    int lane = threadIdx.x & 31;
    int bN = (row / N_) * N_;
    int base = row * CSRCAP;
    int cnt = g_ccnt[row];
    float s = 0.f;
    for (int e = lane; e < cnt; e += 32) {
        int m = g_ccol[base + e];
        s += g_cval[base + e] * __ldg(&g_dg[bN + m]) * __ldg(&g_t[bN + m]);
    }
    #pragma unroll
    for (int o = 16; o; o >>= 1) s += __shfl_xor_sync(0xffffffffu, s, o);
    if (lane == 0) {
        s += g_dg[row] * g_t[row];            // identity part of A_hat
        float pre = g_dg[row] * s + bptr[0];
        float z = pre * pre;
        g_alpha[row] = 1.f / (1.f + expf(-z));
    }
}

// ---- KC: per-batch top-K (bitonic, value desc / index asc) | zero xc+coarse ----
__global__ void k_topk(float* __restrict__ out_all){
    int blk = blockIdx.x;
    int tid = threadIdx.x;
    if (blk >= B_) {
        size_t i = (size_t)(blk - B_) * 1024 + tid;
        float4 z = make_float4(0.f,0.f,0.f,0.f);
        float4* o4 = (float4*)out_all;
        size_t stride = (size_t)TZB * 1024;
        for (; i < FRONT4; i += stride) o4[i] = z;
        return;
    }
    int b = blk;
    float* out_ti = out_all + TI_OFF;
    __shared__ unsigned long long sk[N_];
    __shared__ float cutv;
    __shared__ int acnt;
    for (int i = tid; i < N_; i += 1024) {
        g_rank[b * N_ + i] = -1;
        float v = g_alpha[b * N_ + i];
        unsigned u = __float_as_uint(v);
        u = (u & 0x80000000u) ? ~u : (u | 0x80000000u);
        sk[i] = ((unsigned long long)(~u) << 32) | (unsigned)i;
    }
    __syncthreads();
    for (int k = 2; k <= N_; k <<= 1) {
        for (int j = k >> 1; j > 0; j >>= 1) {
            for (int t = tid; t < N_; t += 1024) {
                int ixj = t ^ j;
                if (ixj > t) {
                    bool up = ((t & k) == 0);
                    unsigned long long a = sk[t], c = sk[ixj];
                    if ((a > c) == up) { sk[t] = c; sk[ixj] = a; }
                }
            }
            __syncthreads();
        }
    }
    if (tid == 0) {
        int idxK = (int)(sk[K_ - 1] & 0xffffffffu);
        cutv = g_alpha[b * N_ + idxK];
        int A = K_;
        while (A < ACAP) {
            int id = (int)(sk[A] & 0xffffffffu);
            float v = g_alpha[b * N_ + id];
            if (v + 1e-7f - cutv > 0.f) A++; else break;
        }
        acnt = A;
        g_acnt[b] = A;
    }
    __syncthreads();
    for (int j = tid; j < acnt; j += 1024) {
        int id = (int)(sk[j] & 0xffffffffu);
        g_colid[b * ACAP + j] = id;
        g_w[b * ACAP + j] = g_alpha[b * N_ + id] + 1e-7f - cutv;
        g_rank[b * N_ + id] = j;
    }
    for (int j = tid; j < K_; j += 1024) {
        int id = (int)(sk[j] & 0xffffffffu);
        out_ti[b * K_ + j] = (float)id;
    }
}

// ---- KD: build normalized S rows (sparse list + dense scatter into zeroed S) ----
__global__ void k_sbuild(float* __restrict__ S_out){
    int row = blockIdx.x * 8 + (threadIdx.x >> 5);
    if (row >= ROWS_) return;
    int lane = threadIdx.x & 31;
    int b = row / N_, n = row % N_;
    if (g_radj[row] <= 0.f) {
        if (lane == 0) g_scnt[row] = 0;
        return;
    }
    float dgn = g_dg[row];
    int cnt = g_ccnt[row], base = row * CSRCAP;
    bool hasdiag = (g_adiag[row] != 0.f);
    float rs = 0.f;
    for (int e = lane; e < cnt; e += 32) {
        int m = g_ccol[base + e];
        int j = g_rank[b * N_ + m];
        if (j >= 0) {
            float ahat = g_cval[base + e] + (m == n ? 1.f : 0.f);
            rs += dgn * ahat * g_dg[b * N_ + m] * g_w[b * ACAP + j];
        }
    }
    if (!hasdiag && lane == 0) {
        int j = g_rank[row];
        if (j >= 0) rs += dgn * dgn * g_w[b * ACAP + j];
    }
    #pragma unroll
    for (int o = 16; o; o >>= 1) rs += __shfl_xor_sync(0xffffffffu, rs, o);
    float inv = 1.f / fmaxf(rs, 1e-12f);
    int sc = 0, sbase = row * SROWCAP;
    for (int c = 0; c < cnt; c += 32) {
        int e = c + lane;
        bool act = false; int j = -1, m = -1; float v = 0.f;
        if (e < cnt) {
            m = g_ccol[base + e];
            j = g_rank[b * N_ + m];
            if (j >= 0) {
                act = true;
                float ahat = g_cval[base + e] + (m == n ? 1.f : 0.f);
                v = dgn * ahat * g_dg[b * N_ + m] * g_w[b * ACAP + j] * inv;
            }
        }
        unsigned msk = __ballot_sync(0xffffffffu, act);
        if (act) {
            int pos = sc + __popc(msk & ((1u << lane) - 1u));
            if (pos < SROWCAP) { g_sj[sbase + pos] = j; g_sv[sbase + pos] = v; }
            S_out[(size_t)row * N_ + m] = v;
        }
        sc += __popc(msk);
    }
    if (!hasdiag) {
        int add = 0;
        if (lane == 0) {
            int j = g_rank[row];
            if (j >= 0) {
                float v = dgn * dgn * g_w[b * ACAP + j] * inv;
                if (sc < SROWCAP) { g_sj[sbase + sc] = j; g_sv[sbase + sc] = v; }
                S_out[(size_t)row * N_ + n] = v;
                add = 1;
            }
        }
        sc += __shfl_sync(0xffffffffu, add, 0);
    }
    if (lane == 0) g_scnt[row] = sc < SROWCAP ? sc : SROWCAP;
}

// ---- KE: T[n,:] = sum_k adj[n,k] * Srow[k]  (warp per row, smem accumulators) ----
__global__ void k_T(){
    int w = threadIdx.x >> 5;
    int row = blockIdx.x * 8 + w;
    int lane = threadIdx.x & 31;
    __shared__ float acc[8][ACAP];
    float* a = acc[w];
    for (int i = lane; i < ACAP; i += 32) a[i] = 0.f;
    __syncwarp();
    int b = row / N_;
    int cnt = g_ccnt[row], base = row * CSRCAP;
    for (int e = lane; e < cnt; e += 32) {
        int k = g_ccol[base + e];
        float av = g_cval[base + e];
        size_t krow = (size_t)b * N_ + k;
        int sb = (int)krow * SROWCAP;
        int sc = g_scnt[krow];
        for (int q = 0; q < sc; q++)
            atomicAdd(&a[g_sj[sb + q]], av * g_sv[sb + q]);
    }
    __syncwarp();
    int A = g_acnt[b];
    float* Trow = g_T + (size_t)row * ACAP;
    for (int j = lane; j < A; j += 32) Trow[j] = a[j];
}

// ---- KF: fused coarse + x_c (direct coalesced loads, Round-3 style) ----
__global__ void __launch_bounds__(256) k_cx(
        const float* __restrict__ x, const float* __restrict__ S_out,
        float* __restrict__ out_co, float* __restrict__ out_xc){
    int b = blockIdx.y;
    int jm = blockIdx.x;
    int A = g_acnt[b];
    if (jm >= A) return;
    int tid = threadIdx.x;
    int m = g_colid[b * ACAP + jm];
    size_t bN = (size_t)b * N_;
    size_t mrow = bN + m;
    __shared__ int   sn[CSRCAP + 1];
    __shared__ float sv[CSRCAP + 1];
    int cnt = g_ccnt[mrow], base = (int)mrow * CSRCAP;
    if (tid < cnt) {
        int n2 = g_ccol[base + tid];
        sn[tid] = n2;
        sv[tid] = S_out[(bN + n2) * N_ + m];   // symmetry: col m pattern = row m
    }
    int tot = cnt;
    if (g_adiag[mrow] == 0.f) {
        if (tid == 0) { sn[cnt] = m; sv[cnt] = S_out[mrow * N_ + m]; }
        tot = cnt + 1;
    }
    __syncthreads();
    // x_c: tid = feature index (F_ == blockDim.x == 256)
    {
        float acc = 0.f;
        for (int e = 0; e < tot; e++)
            acc += sv[e] * x[(bN + sn[e]) * F_ + tid];
        out_xc[mrow * F_ + tid] = acc;
    }
    // coarse: active block column jm, all active rows j (A <= 256 == blockDim)
    if (tid < A) {
        float acc = 0.f;
        for (int e = 0; e < tot; e++)
            acc += sv[e] * g_T[(bN + sn[e]) * ACAP + tid];
        float c = floorf(acc * 10000.0f) / 10000.0f;
        int l = g_colid[b * ACAP + tid];
        out_co[mrow * N_ + l] = c;
    }
}

extern "C" void kernel_launch(void* const* d_in, const int* in_sizes, int n_in,
                              void* d_out, int out_size) {
    const float* x   = (const float*)d_in[0];
    const float* adj = (const float*)d_in[1];
    const float* W   = (const float*)d_in[2];
    const float* bb  = (const float*)d_in[3];
    float* out = (float*)d_out;

    kA      <<<4096, 256>>>(adj, x, W);
    k_alpha <<<2048 + AZB, 256>>>(bb, out + SO_OFF);
    k_topk  <<<B_ + TZB, 1024>>>(out);
    k_sbuild<<<ROWS_ / 8, 256>>>(out + SO_OFF);
    k_T     <<<ROWS_ / 8, 256>>>();
    dim3 gblk(ACAP, B_);
    k_cx    <<<gblk, 256>>>(x, out + SO_OFF, out + CO_OFF, out + XC_OFF);
}